// round 11
// baseline (speedup 1.0000x reference)
#include <cuda_runtime.h>
#include <cuda_fp16.h>
#include <stdint.h>

// ---------------- problem constants ----------------
#define TT 4
#define NN 8192
#define DD 1024
#define NE 8
#define FF 512
#define KTOP 2
#define NSLOT   (NN * KTOP)              // 16384
#define MAXSLOT (NSLOT + NE * 32)        // 16640
#define MTILES  (MAXSLOT / 32)           // 520

#define BETA 0.9f
#define THRESH 1.0f
#define LSC 128.0f                        // 2^7 residual scale

// k_up smem (r10): rows padded to 40 halves (80B) -> conflict-free ldmatrix
#define RPAD 40
#define T128 (128 * RPAD * 2)            // 10240
#define UP_SA_H 0
#define UP_SA_L (1 * T128)
#define UP_SB_H (2 * T128)
#define UP_SB_L (3 * T128)
#define UP_STRIDE (4 * T128)             // 40960
#define UP_SMEM (2 * UP_STRIDE)          // 81920

// k_down persistent-B smem: 64 rows x 520 halves (1040 B = 65x16B, odd -> conflict-free)
#define DN_ROWB 1040
#define DN_BL_OFF (64 * DN_ROWB)         // 66560
#define DN_SMEM (2 * 64 * DN_ROWB)       // 133120

// ---------------- scratch ----------------
// spikes in MMA A-fragment layout: [tile_m][gk(32)][b(8)][lane(32)][w(4)] u32 words
__device__ uint32_t g_hf[(size_t)MTILES * 32 * 8 * 32 * 4];
__device__ int   g_tok[MAXSLOT];
__device__ float g_gate[MAXSLOT];
__device__ int   g_exp[MAXSLOT];
__device__ int   g_cur[NE];
__device__ int   g_off[NE + 1];

// ---------------- helpers ----------------
__device__ __forceinline__ uint32_t smem_u32(const void* p) {
    uint32_t a;
    asm("{ .reg .u64 t; cvta.to.shared.u64 t, %1; cvt.u32.u64 %0, t; }" : "=r"(a) : "l"(p));
    return a;
}
__device__ __forceinline__ void ldsm4(uint32_t* r, uint32_t a) {
    asm volatile("ldmatrix.sync.aligned.m8n8.x4.shared.b16 {%0,%1,%2,%3}, [%4];"
        : "=r"(r[0]), "=r"(r[1]), "=r"(r[2]), "=r"(r[3]) : "r"(a));
}
__device__ __forceinline__ void mma16816(float* c, const uint32_t* a, const uint32_t* b) {
    asm volatile("mma.sync.aligned.m16n8k16.row.col.f32.f16.f16.f32 "
        "{%0,%1,%2,%3},{%4,%5,%6,%7},{%8,%9},{%0,%1,%2,%3};"
        : "+f"(c[0]), "+f"(c[1]), "+f"(c[2]), "+f"(c[3])
        : "r"(a[0]), "r"(a[1]), "r"(a[2]), "r"(a[3]), "r"(b[0]), "r"(b[1]));
}
// packed fp16 multiply by 2^-7 (exact exponent shift in normal range)
__device__ __forceinline__ uint32_t h2dn7(uint32_t a) {
    uint32_t r;
    asm("mul.f16x2 %0, %1, %2;" : "=r"(r) : "r"(a), "r"(0x20002000u));
    return r;
}

// split 8 fp32 -> h (4 u32 packed fp16x2) and l = rn16((v-h)*2^7) (4 u32)
__device__ __forceinline__ void split8p(const float* f, uint32_t* hp, uint32_t* lp) {
#pragma unroll
    for (int i = 0; i < 4; i++) {
        float f0 = f[2 * i], f1 = f[2 * i + 1];
        __half2 hh = __floats2half2_rn(f0, f1);
        float r0 = (f0 - __low2float(hh)) * LSC;
        float r1 = (f1 - __high2float(hh)) * LSC;
        __half2 ll = __floats2half2_rn(r0, r1);
        hp[i] = *(uint32_t*)&hh;
        lp[i] = *(uint32_t*)&ll;
    }
}

// LIF across 4 timestep-lanes (stride-4 shuffle); returns this lane's own-t spikes
__device__ __forceinline__ void lif4(float v0, float v1, int srcb, int own_t,
                                     float& sp0, float& sp1) {
    float m0 = 0.f, m1 = 0.f;
    sp0 = 0.f; sp1 = 0.f;
#pragma unroll
    for (int t4 = 0; t4 < 4; t4++) {
        float u0 = __shfl_sync(0xffffffffu, v0, srcb + 4 * t4);
        float u1 = __shfl_sync(0xffffffffu, v1, srcb + 4 * t4);
        m0 = BETA * m0 + u0; float s0 = (m0 > THRESH) ? 1.f : 0.f; m0 -= s0 * THRESH;
        m1 = BETA * m1 + u1; float s1 = (m1 > THRESH) ? 1.f : 0.f; m1 -= s1 * THRESH;
        if (t4 == own_t) { sp0 = s0; sp1 = s1; }
    }
}

// ---------------- routing / zero ----------------
__global__ void k_route(const int* __restrict__ idx, const float* __restrict__ wts) {
    __shared__ int scnt[NE];
    int tid = threadIdx.x;
    if (tid < NE) scnt[tid] = 0;
    __syncthreads();
    for (int i = tid; i < NSLOT; i += 512) atomicAdd(&scnt[idx[i]], 1);
    __syncthreads();
    if (tid == 0) {
        int off = 0;
        for (int e = 0; e < NE; e++) {
            g_off[e] = off; g_cur[e] = off;
            off += (scnt[e] + 31) & ~31;
        }
        g_off[NE] = off;
    }
    __syncthreads();
    for (int s = tid; s < MAXSLOT; s += 512) {
        g_tok[s] = -1; g_gate[s] = 0.f;
        int e = 0;
#pragma unroll
        for (int q = 1; q < NE; q++) if (s >= g_off[q]) e = q;
        g_exp[s] = e;
    }
    __syncthreads();
    for (int i = tid; i < NSLOT; i += 512) {
        int e = idx[i];
        int p = atomicAdd(&g_cur[e], 1);
        g_tok[p] = i >> 1;
        g_gate[p] = wts[i];
    }
}
__global__ void k_zero(float4* out, int n4) {
    int stride = gridDim.x * blockDim.x;
    for (int i = blockIdx.x * blockDim.x + threadIdx.x; i < n4; i += stride)
        out[i] = make_float4(0.f, 0.f, 0.f, 0.f);
}

// ---------------- up compute chunk (r10, unchanged) ----------------
__device__ __forceinline__ void comp_up(uint32_t bufb, int lane, int wm, int wn,
                                        float (&acc)[2][4][4]) {
#pragma unroll
    for (int k16 = 0; k16 < 2; k16++) {
        uint32_t koff = k16 * 16 + ((lane >> 4) << 3);
        uint32_t aoff = ((wm * 32 + (lane & 15)) * RPAD + koff) * 2;
        uint32_t ah[2][4], al[2][4];
        ldsm4(ah[0], bufb + UP_SA_H + aoff);
        ldsm4(ah[1], bufb + UP_SA_H + aoff + 16 * RPAD * 2);
        ldsm4(al[0], bufb + UP_SA_L + aoff);
        ldsm4(al[1], bufb + UP_SA_L + aoff + 16 * RPAD * 2);
        uint32_t boff = ((wn * 32 + (lane & 15)) * RPAD + koff) * 2;
        uint32_t bh[4][2], bl[4][2], bhs[4][2];
#pragma unroll
        for (int g = 0; g < 2; g++) {
            uint32_t r[4];
            ldsm4(r, bufb + UP_SB_H + boff + g * 16 * RPAD * 2);
            bh[2 * g][0] = r[0]; bh[2 * g][1] = r[2];
            bh[2 * g + 1][0] = r[1]; bh[2 * g + 1][1] = r[3];
            ldsm4(r, bufb + UP_SB_L + boff + g * 16 * RPAD * 2);
            bl[2 * g][0] = r[0]; bl[2 * g][1] = r[2];
            bl[2 * g + 1][0] = r[1]; bl[2 * g + 1][1] = r[3];
        }
        uint32_t ahs[2][4];
#pragma unroll
        for (int im = 0; im < 2; im++)
#pragma unroll
            for (int q = 0; q < 4; q++) ahs[im][q] = h2dn7(ah[im][q]);
#pragma unroll
        for (int j = 0; j < 4; j++) { bhs[j][0] = h2dn7(bh[j][0]); bhs[j][1] = h2dn7(bh[j][1]); }
#pragma unroll
        for (int im = 0; im < 2; im++)
#pragma unroll
            for (int j = 0; j < 4; j++) {
                mma16816(acc[im][j], ah[im], bh[j]);    // xh*wh
                mma16816(acc[im][j], ahs[im], bl[j]);   // (xh*2^-7)*(res_w*2^7)
                mma16816(acc[im][j], al[im], bhs[j]);   // (res_x*2^7)*(wh*2^-7)
            }
    }
}

// ---------------- up-proj + LIF -> fragment-layout fp16 spikes (r10, unchanged) ----------------
__global__ __launch_bounds__(512, 1)
void k_up(const float* __restrict__ x, const float* __restrict__ upw) {
    const int tile_m = blockIdx.y, sbase = tile_m * 32;
    if (sbase >= g_off[NE]) return;
    const int e = g_exp[sbase];
    const int fbase = blockIdx.x * 128;

    extern __shared__ char smem[];
    const uint32_t sb = smem_u32(smem);
    const int tid = threadIdx.x, lane = tid & 31, warp = tid >> 5;
    const int wm = warp >> 2, wn = warp & 3;

    const int lrowA = tid >> 2, aq = (tid & 3) * 8;
    int tok = g_tok[sbase + (lrowA >> 2)];
    if (tok < 0) tok = 0;
    const float* aptr = x + ((size_t)(lrowA & 3) * NN + tok) * DD + aq;
    const uint32_t stsA = (uint32_t)(lrowA * RPAD + aq) * 2;
    const int lrowB = tid >> 2, bq = (tid & 3) * 8;
    const float* bptr = upw + ((size_t)e * FF + fbase + lrowB) * DD + bq;
    const uint32_t stsB = (uint32_t)(lrowB * RPAD + bq) * 2;

    float acc[2][4][4];
#pragma unroll
    for (int im = 0; im < 2; im++)
#pragma unroll
        for (int j = 0; j < 4; j++)
#pragma unroll
            for (int q = 0; q < 4; q++) acc[im][j][q] = 0.f;

    float fA[8], fB[8];
#pragma unroll
    for (int q = 0; q < 2; q++) {
        float4 v = *(const float4*)(aptr + q * 4);
        fA[4 * q] = v.x; fA[4 * q + 1] = v.y; fA[4 * q + 2] = v.z; fA[4 * q + 3] = v.w;
        float4 w = *(const float4*)(bptr + q * 4);
        fB[4 * q] = w.x; fB[4 * q + 1] = w.y; fB[4 * q + 2] = w.z; fB[4 * q + 3] = w.w;
    }
    {
        uint32_t h[4], l[4];
        split8p(fA, h, l);
        *(uint4*)(smem + UP_SA_H + stsA) = make_uint4(h[0], h[1], h[2], h[3]);
        *(uint4*)(smem + UP_SA_L + stsA) = make_uint4(l[0], l[1], l[2], l[3]);
        split8p(fB, h, l);
        *(uint4*)(smem + UP_SB_H + stsB) = make_uint4(h[0], h[1], h[2], h[3]);
        *(uint4*)(smem + UP_SB_L + stsB) = make_uint4(l[0], l[1], l[2], l[3]);
    }
    __syncthreads();

    const int NC = DD / 32;   // 32
    for (int c = 0; c < NC; c++) {
        const int buf = c & 1;
        if (c + 1 < NC) {
#pragma unroll
            for (int q = 0; q < 2; q++) {
                float4 v = *(const float4*)(aptr + (c + 1) * 32 + q * 4);
                fA[4 * q] = v.x; fA[4 * q + 1] = v.y; fA[4 * q + 2] = v.z; fA[4 * q + 3] = v.w;
                float4 w = *(const float4*)(bptr + (c + 1) * 32 + q * 4);
                fB[4 * q] = w.x; fB[4 * q + 1] = w.y; fB[4 * q + 2] = w.z; fB[4 * q + 3] = w.w;
            }
        }
        comp_up(sb + buf * UP_STRIDE, lane, wm, wn, acc);
        if (c + 1 < NC) {
            char* nb = smem + (buf ^ 1) * UP_STRIDE;
            uint32_t h[4], l[4];
            split8p(fA, h, l);
            *(uint4*)(nb + UP_SA_H + stsA) = make_uint4(h[0], h[1], h[2], h[3]);
            *(uint4*)(nb + UP_SA_L + stsA) = make_uint4(l[0], l[1], l[2], l[3]);
            split8p(fB, h, l);
            *(uint4*)(nb + UP_SB_H + stsB) = make_uint4(h[0], h[1], h[2], h[3]);
            *(uint4*)(nb + UP_SB_L + stsB) = make_uint4(l[0], l[1], l[2], l[3]);
        }
        __syncthreads();
    }

    const int cg = lane & 3;
    const int srcb = (lane & 16) + cg;
    const int own_t = (lane >> 2) & 3;
#pragma unroll
    for (int im = 0; im < 2; im++)
#pragma unroll
        for (int j = 0; j < 4; j++) {
            float sp0, sp1, sp2, sp3;
            lif4(acc[im][j][0], acc[im][j][1], srcb, own_t, sp0, sp1);
            lif4(acc[im][j][2], acc[im][j][3], srcb, own_t, sp2, sp3);
            const int g = blockIdx.x * 8 + wn * 2 + (j >> 1);
            const int b = wm * 2 + im;
            const size_t widx = ((((size_t)tile_m * 32 + g) * 8 + b) * 32 + lane) * 4 + (j & 1) * 2;
            __half2 w0 = __floats2half2_rn(sp0, sp1);
            __half2 w1 = __floats2half2_rn(sp2, sp3);
            *(uint2*)&g_hf[widx] = make_uint2(*(uint32_t*)&w0, *(uint32_t*)&w1);
        }
}

// ---------------- down-proj: persistent split-B, loop m-tiles ----------------
// grid (DD/64=16, NE=8) = 128 CTAs, 256 thr. B tile (64 x 512) split once into smem,
// then all of the expert's m-tiles computed with zero barriers.
__global__ __launch_bounds__(256, 1)
void k_down(const float* __restrict__ dww, float* __restrict__ out) {
    const int e = blockIdx.y;
    const int dbase = blockIdx.x * 64;
    const int mt0 = g_off[e] >> 5, mt1 = g_off[e + 1] >> 5;
    if (mt0 >= mt1) return;

    extern __shared__ char smem[];
    const uint32_t sb = smem_u32(smem);
    const int tid = threadIdx.x, lane = tid & 31, warp = tid >> 5;
    const int wm = warp >> 1, wn = warp & 1;

    // one-time: load + split whole B tile (64 rows x 512 k)
    {
        const int row = tid >> 2;
        const int seg = (tid & 3) * 128;
        const float* bp = dww + ((size_t)e * DD + dbase + row) * FF + seg;
        char* hb = smem + (uint32_t)row * DN_ROWB + seg * 2;
        char* lb = smem + DN_BL_OFF + (uint32_t)row * DN_ROWB + seg * 2;
        for (int k = 0; k < 128; k += 8) {
            float f[8];
            float4 v0 = *(const float4*)(bp + k);
            float4 v1 = *(const float4*)(bp + k + 4);
            f[0] = v0.x; f[1] = v0.y; f[2] = v0.z; f[3] = v0.w;
            f[4] = v1.x; f[5] = v1.y; f[6] = v1.z; f[7] = v1.w;
            uint32_t h[4], l[4];
            split8p(f, h, l);
            *(uint4*)(hb + k * 2) = make_uint4(h[0], h[1], h[2], h[3]);
            *(uint4*)(lb + k * 2) = make_uint4(l[0], l[1], l[2], l[3]);
        }
    }
    __syncthreads();

    const uint4* af = (const uint4*)g_hf;
    const int cg = lane & 3;
    const int srcb = (lane & 16) + cg;
    const int own_t = (lane >> 2) & 3;
    const uint32_t bcol = (uint32_t)(wn * 32 + (lane & 15)) * DN_ROWB;
    const uint32_t kphase = ((uint32_t)(lane >> 4) << 3) * 2;

    for (int tile_m = mt0; tile_m < mt1; tile_m++) {
        const int sbase = tile_m * 32;
        const size_t abase = (((size_t)tile_m * 32) * 8 + (wm * 2)) * 32 + lane;

        float acc[2][4][4];
#pragma unroll
        for (int im = 0; im < 2; im++)
#pragma unroll
            for (int j = 0; j < 4; j++)
#pragma unroll
                for (int q = 0; q < 4; q++) acc[im][j][q] = 0.f;

        uint4 Acur[4];
#pragma unroll
        for (int k16 = 0; k16 < 2; k16++)
#pragma unroll
            for (int im = 0; im < 2; im++)
                Acur[k16 * 2 + im] = af[abase + (size_t)k16 * 256 + im * 32];

        for (int p = 0; p < 16; p++) {
            uint4 Anext[4];
            if (p < 15) {
#pragma unroll
                for (int k16 = 0; k16 < 2; k16++)
#pragma unroll
                    for (int im = 0; im < 2; im++)
                        Anext[k16 * 2 + im] = af[abase + (size_t)(2 * (p + 1) + k16) * 256 + im * 32];
            }
#pragma unroll
            for (int k16 = 0; k16 < 2; k16++) {
                const uint32_t koff2 = (uint32_t)((2 * p + k16) * 16) * 2 + kphase;
                const uint32_t boff = bcol + koff2;
                uint32_t as_[2][4], ass[2][4];
#pragma unroll
                for (int im = 0; im < 2; im++) {
                    const uint4 a = Acur[k16 * 2 + im];
                    as_[im][0] = a.x; as_[im][1] = a.y; as_[im][2] = a.z; as_[im][3] = a.w;
#pragma unroll
                    for (int q = 0; q < 4; q++) ass[im][q] = h2dn7(as_[im][q]);
                }
                uint32_t bh[4][2], bl[4][2];
#pragma unroll
                for (int g = 0; g < 2; g++) {
                    uint32_t r[4];
                    ldsm4(r, sb + boff + g * 16 * DN_ROWB);
                    bh[2 * g][0] = r[0]; bh[2 * g][1] = r[2];
                    bh[2 * g + 1][0] = r[1]; bh[2 * g + 1][1] = r[3];
                    ldsm4(r, sb + DN_BL_OFF + boff + g * 16 * DN_ROWB);
                    bl[2 * g][0] = r[0]; bl[2 * g][1] = r[2];
                    bl[2 * g + 1][0] = r[1]; bl[2 * g + 1][1] = r[3];
                }
#pragma unroll
                for (int im = 0; im < 2; im++)
#pragma unroll
                    for (int j = 0; j < 4; j++) {
                        mma16816(acc[im][j], as_[im], bh[j]);   // s*wh
                        mma16816(acc[im][j], ass[im], bl[j]);   // (s*2^-7)*(res_w*2^7)
                    }
            }
            if (p < 15) {
#pragma unroll
                for (int q = 0; q < 4; q++) Acur[q] = Anext[q];
            }
        }

        // epilogue: LIF + gated atomic scatter
#pragma unroll
        for (int im = 0; im < 2; im++)
#pragma unroll
            for (int j = 0; j < 4; j++) {
                float sp0, sp1, sp2, sp3;
                lif4(acc[im][j][0], acc[im][j][1], srcb, own_t, sp0, sp1);
                lif4(acc[im][j][2], acc[im][j][3], srcb, own_t, sp2, sp3);
                const int mloc = wm * 32 + im * 16 + (lane >> 2);
                const int col = dbase + wn * 32 + j * 8 + 2 * cg;
                {
                    const int slot = sbase + (mloc >> 2);
                    const int tok = g_tok[slot];
                    if (tok >= 0 && (sp0 != 0.f || sp1 != 0.f)) {
                        const float gate = g_gate[slot];
                        float* op = out + ((size_t)own_t * NN + tok) * DD + col;
                        if (sp0 != 0.f) atomicAdd(op, gate);
                        if (sp1 != 0.f) atomicAdd(op + 1, gate);
                    }
                }
                {
                    const int slot = sbase + ((mloc + 8) >> 2);
                    const int tok = g_tok[slot];
                    if (tok >= 0 && (sp2 != 0.f || sp3 != 0.f)) {
                        const float gate = g_gate[slot];
                        float* op = out + ((size_t)own_t * NN + tok) * DD + col;
                        if (sp2 != 0.f) atomicAdd(op, gate);
                        if (sp3 != 0.f) atomicAdd(op + 1, gate);
                    }
                }
            }
    }
}

// ---------------- launch ----------------
extern "C" void kernel_launch(void* const* d_in, const int* in_sizes, int n_in,
                              void* d_out, int out_size) {
    const float* x    = (const float*)d_in[0];
    const int*   idx  = (const int*)d_in[1];
    const float* wts  = (const float*)d_in[2];
    const float* upw  = (const float*)d_in[3];
    const float* dww  = (const float*)d_in[4];
    float* out = (float*)d_out;
    (void)in_sizes; (void)n_in; (void)out_size;

    cudaFuncSetAttribute(k_up,   cudaFuncAttributeMaxDynamicSharedMemorySize, UP_SMEM);
    cudaFuncSetAttribute(k_down, cudaFuncAttributeMaxDynamicSharedMemorySize, DN_SMEM);

    k_zero<<<4096, 256>>>((float4*)out, TT * NN * DD / 4);
    k_route<<<1, 512>>>(idx, wts);
    k_up<<<dim3(FF / 128, MTILES), 512, UP_SMEM>>>(x, upw);
    k_down<<<dim3(DD / 64, NE), 256, DN_SMEM>>>(dww, out);
}

// round 12
// speedup vs baseline: 1.0473x; 1.0473x over previous
#include <cuda_runtime.h>
#include <cuda_fp16.h>
#include <stdint.h>

// ---------------- problem constants ----------------
#define TT 4
#define NN 8192
#define DD 1024
#define NE 8
#define FF 512
#define KTOP 2
#define NSLOT   (NN * KTOP)              // 16384
#define MAXSLOT (NSLOT + NE * 32)        // 16640
#define MTILES  (MAXSLOT / 32)           // 520

#define BETA 0.9f
#define THRESH 1.0f
#define LSC 128.0f                        // 2^7 residual scale

// k_up smem (r10): rows padded to 40 halves (80B) -> conflict-free ldmatrix
#define RPAD 40
#define T128 (128 * RPAD * 2)            // 10240
#define UP_SA_H 0
#define UP_SA_L (1 * T128)
#define UP_SB_H (2 * T128)
#define UP_SB_L (3 * T128)
#define UP_STRIDE (4 * T128)             // 40960
#define UP_SMEM (2 * UP_STRIDE)          // 81920

// k_down persistent-B smem: 64 rows x 520 halves (1040 B = 65x16B, odd -> conflict-free)
#define DN_ROWB 1040
#define DN_BL_OFF (64 * DN_ROWB)         // 66560
#define DN_SMEM (2 * 64 * DN_ROWB)       // 133120

// ---------------- scratch ----------------
// spikes in MMA A-fragment layout: [tile_m][gk(32)][b(8)][lane(32)][w(4)] u32 words
__device__ uint32_t g_hf[(size_t)MTILES * 32 * 8 * 32 * 4];
__device__ int   g_tok[MAXSLOT];
__device__ float g_gate[MAXSLOT];
__device__ int   g_exp[MAXSLOT];
__device__ int   g_cur[NE];
__device__ int   g_off[NE + 1];

// ---------------- helpers ----------------
__device__ __forceinline__ uint32_t smem_u32(const void* p) {
    uint32_t a;
    asm("{ .reg .u64 t; cvta.to.shared.u64 t, %1; cvt.u32.u64 %0, t; }" : "=r"(a) : "l"(p));
    return a;
}
__device__ __forceinline__ void ldsm4(uint32_t* r, uint32_t a) {
    asm volatile("ldmatrix.sync.aligned.m8n8.x4.shared.b16 {%0,%1,%2,%3}, [%4];"
        : "=r"(r[0]), "=r"(r[1]), "=r"(r[2]), "=r"(r[3]) : "r"(a));
}
__device__ __forceinline__ void mma16816(float* c, const uint32_t* a, const uint32_t* b) {
    asm volatile("mma.sync.aligned.m16n8k16.row.col.f32.f16.f16.f32 "
        "{%0,%1,%2,%3},{%4,%5,%6,%7},{%8,%9},{%0,%1,%2,%3};"
        : "+f"(c[0]), "+f"(c[1]), "+f"(c[2]), "+f"(c[3])
        : "r"(a[0]), "r"(a[1]), "r"(a[2]), "r"(a[3]), "r"(b[0]), "r"(b[1]));
}
// packed fp16 multiply by 2^-7 (exact exponent shift in normal range)
__device__ __forceinline__ uint32_t h2dn7(uint32_t a) {
    uint32_t r;
    asm("mul.f16x2 %0, %1, %2;" : "=r"(r) : "r"(a), "r"(0x20002000u));
    return r;
}

// split 8 fp32 -> h (4 u32 packed fp16x2) and l = rn16((v-h)*2^7) (4 u32)
__device__ __forceinline__ void split8p(const float* f, uint32_t* hp, uint32_t* lp) {
#pragma unroll
    for (int i = 0; i < 4; i++) {
        float f0 = f[2 * i], f1 = f[2 * i + 1];
        __half2 hh = __floats2half2_rn(f0, f1);
        float r0 = (f0 - __low2float(hh)) * LSC;
        float r1 = (f1 - __high2float(hh)) * LSC;
        __half2 ll = __floats2half2_rn(r0, r1);
        hp[i] = *(uint32_t*)&hh;
        lp[i] = *(uint32_t*)&ll;
    }
}

// LIF across 4 timestep-lanes (stride-4 shuffle); returns this lane's own-t spikes
__device__ __forceinline__ void lif4(float v0, float v1, int srcb, int own_t,
                                     float& sp0, float& sp1) {
    float m0 = 0.f, m1 = 0.f;
    sp0 = 0.f; sp1 = 0.f;
#pragma unroll
    for (int t4 = 0; t4 < 4; t4++) {
        float u0 = __shfl_sync(0xffffffffu, v0, srcb + 4 * t4);
        float u1 = __shfl_sync(0xffffffffu, v1, srcb + 4 * t4);
        m0 = BETA * m0 + u0; float s0 = (m0 > THRESH) ? 1.f : 0.f; m0 -= s0 * THRESH;
        m1 = BETA * m1 + u1; float s1 = (m1 > THRESH) ? 1.f : 0.f; m1 -= s1 * THRESH;
        if (t4 == own_t) { sp0 = s0; sp1 = s1; }
    }
}

// ---------------- routing / zero ----------------
__global__ void k_route(const int* __restrict__ idx, const float* __restrict__ wts) {
    __shared__ int scnt[NE];
    int tid = threadIdx.x;
    if (tid < NE) scnt[tid] = 0;
    __syncthreads();
    for (int i = tid; i < NSLOT; i += 512) atomicAdd(&scnt[idx[i]], 1);
    __syncthreads();
    if (tid == 0) {
        int off = 0;
        for (int e = 0; e < NE; e++) {
            g_off[e] = off; g_cur[e] = off;
            off += (scnt[e] + 31) & ~31;
        }
        g_off[NE] = off;
    }
    __syncthreads();
    for (int s = tid; s < MAXSLOT; s += 512) {
        g_tok[s] = -1; g_gate[s] = 0.f;
        int e = 0;
#pragma unroll
        for (int q = 1; q < NE; q++) if (s >= g_off[q]) e = q;
        g_exp[s] = e;
    }
    __syncthreads();
    for (int i = tid; i < NSLOT; i += 512) {
        int e = idx[i];
        int p = atomicAdd(&g_cur[e], 1);
        g_tok[p] = i >> 1;
        g_gate[p] = wts[i];
    }
}
__global__ void k_zero(float4* out, int n4) {
    int stride = gridDim.x * blockDim.x;
    for (int i = blockIdx.x * blockDim.x + threadIdx.x; i < n4; i += stride)
        out[i] = make_float4(0.f, 0.f, 0.f, 0.f);
}

// ---------------- up compute chunk (r10, unchanged) ----------------
__device__ __forceinline__ void comp_up(uint32_t bufb, int lane, int wm, int wn,
                                        float (&acc)[2][4][4]) {
#pragma unroll
    for (int k16 = 0; k16 < 2; k16++) {
        uint32_t koff = k16 * 16 + ((lane >> 4) << 3);
        uint32_t aoff = ((wm * 32 + (lane & 15)) * RPAD + koff) * 2;
        uint32_t ah[2][4], al[2][4];
        ldsm4(ah[0], bufb + UP_SA_H + aoff);
        ldsm4(ah[1], bufb + UP_SA_H + aoff + 16 * RPAD * 2);
        ldsm4(al[0], bufb + UP_SA_L + aoff);
        ldsm4(al[1], bufb + UP_SA_L + aoff + 16 * RPAD * 2);
        uint32_t boff = ((wn * 32 + (lane & 15)) * RPAD + koff) * 2;
        uint32_t bh[4][2], bl[4][2], bhs[4][2];
#pragma unroll
        for (int g = 0; g < 2; g++) {
            uint32_t r[4];
            ldsm4(r, bufb + UP_SB_H + boff + g * 16 * RPAD * 2);
            bh[2 * g][0] = r[0]; bh[2 * g][1] = r[2];
            bh[2 * g + 1][0] = r[1]; bh[2 * g + 1][1] = r[3];
            ldsm4(r, bufb + UP_SB_L + boff + g * 16 * RPAD * 2);
            bl[2 * g][0] = r[0]; bl[2 * g][1] = r[2];
            bl[2 * g + 1][0] = r[1]; bl[2 * g + 1][1] = r[3];
        }
        uint32_t ahs[2][4];
#pragma unroll
        for (int im = 0; im < 2; im++)
#pragma unroll
            for (int q = 0; q < 4; q++) ahs[im][q] = h2dn7(ah[im][q]);
#pragma unroll
        for (int j = 0; j < 4; j++) { bhs[j][0] = h2dn7(bh[j][0]); bhs[j][1] = h2dn7(bh[j][1]); }
#pragma unroll
        for (int im = 0; im < 2; im++)
#pragma unroll
            for (int j = 0; j < 4; j++) {
                mma16816(acc[im][j], ah[im], bh[j]);    // xh*wh
                mma16816(acc[im][j], ahs[im], bl[j]);   // (xh*2^-7)*(res_w*2^7)
                mma16816(acc[im][j], al[im], bhs[j]);   // (res_x*2^7)*(wh*2^-7)
            }
    }
}

// ---------------- up-proj + LIF -> fragment-layout fp16 spikes (r10, unchanged) ----------------
__global__ __launch_bounds__(512, 1)
void k_up(const float* __restrict__ x, const float* __restrict__ upw) {
    const int tile_m = blockIdx.y, sbase = tile_m * 32;
    if (sbase >= g_off[NE]) return;
    const int e = g_exp[sbase];
    const int fbase = blockIdx.x * 128;

    extern __shared__ char smem[];
    const uint32_t sb = smem_u32(smem);
    const int tid = threadIdx.x, lane = tid & 31, warp = tid >> 5;
    const int wm = warp >> 2, wn = warp & 3;

    const int lrowA = tid >> 2, aq = (tid & 3) * 8;
    int tok = g_tok[sbase + (lrowA >> 2)];
    if (tok < 0) tok = 0;
    const float* aptr = x + ((size_t)(lrowA & 3) * NN + tok) * DD + aq;
    const uint32_t stsA = (uint32_t)(lrowA * RPAD + aq) * 2;
    const int lrowB = tid >> 2, bq = (tid & 3) * 8;
    const float* bptr = upw + ((size_t)e * FF + fbase + lrowB) * DD + bq;
    const uint32_t stsB = (uint32_t)(lrowB * RPAD + bq) * 2;

    float acc[2][4][4];
#pragma unroll
    for (int im = 0; im < 2; im++)
#pragma unroll
        for (int j = 0; j < 4; j++)
#pragma unroll
            for (int q = 0; q < 4; q++) acc[im][j][q] = 0.f;

    float fA[8], fB[8];
#pragma unroll
    for (int q = 0; q < 2; q++) {
        float4 v = *(const float4*)(aptr + q * 4);
        fA[4 * q] = v.x; fA[4 * q + 1] = v.y; fA[4 * q + 2] = v.z; fA[4 * q + 3] = v.w;
        float4 w = *(const float4*)(bptr + q * 4);
        fB[4 * q] = w.x; fB[4 * q + 1] = w.y; fB[4 * q + 2] = w.z; fB[4 * q + 3] = w.w;
    }
    {
        uint32_t h[4], l[4];
        split8p(fA, h, l);
        *(uint4*)(smem + UP_SA_H + stsA) = make_uint4(h[0], h[1], h[2], h[3]);
        *(uint4*)(smem + UP_SA_L + stsA) = make_uint4(l[0], l[1], l[2], l[3]);
        split8p(fB, h, l);
        *(uint4*)(smem + UP_SB_H + stsB) = make_uint4(h[0], h[1], h[2], h[3]);
        *(uint4*)(smem + UP_SB_L + stsB) = make_uint4(l[0], l[1], l[2], l[3]);
    }
    __syncthreads();

    const int NC = DD / 32;   // 32
    for (int c = 0; c < NC; c++) {
        const int buf = c & 1;
        if (c + 1 < NC) {
#pragma unroll
            for (int q = 0; q < 2; q++) {
                float4 v = *(const float4*)(aptr + (c + 1) * 32 + q * 4);
                fA[4 * q] = v.x; fA[4 * q + 1] = v.y; fA[4 * q + 2] = v.z; fA[4 * q + 3] = v.w;
                float4 w = *(const float4*)(bptr + (c + 1) * 32 + q * 4);
                fB[4 * q] = w.x; fB[4 * q + 1] = w.y; fB[4 * q + 2] = w.z; fB[4 * q + 3] = w.w;
            }
        }
        comp_up(sb + buf * UP_STRIDE, lane, wm, wn, acc);
        if (c + 1 < NC) {
            char* nb = smem + (buf ^ 1) * UP_STRIDE;
            uint32_t h[4], l[4];
            split8p(fA, h, l);
            *(uint4*)(nb + UP_SA_H + stsA) = make_uint4(h[0], h[1], h[2], h[3]);
            *(uint4*)(nb + UP_SA_L + stsA) = make_uint4(l[0], l[1], l[2], l[3]);
            split8p(fB, h, l);
            *(uint4*)(nb + UP_SB_H + stsB) = make_uint4(h[0], h[1], h[2], h[3]);
            *(uint4*)(nb + UP_SB_L + stsB) = make_uint4(l[0], l[1], l[2], l[3]);
        }
        __syncthreads();
    }

    const int cg = lane & 3;
    const int srcb = (lane & 16) + cg;
    const int own_t = (lane >> 2) & 3;
#pragma unroll
    for (int im = 0; im < 2; im++)
#pragma unroll
        for (int j = 0; j < 4; j++) {
            float sp0, sp1, sp2, sp3;
            lif4(acc[im][j][0], acc[im][j][1], srcb, own_t, sp0, sp1);
            lif4(acc[im][j][2], acc[im][j][3], srcb, own_t, sp2, sp3);
            const int g = blockIdx.x * 8 + wn * 2 + (j >> 1);
            const int b = wm * 2 + im;
            const size_t widx = ((((size_t)tile_m * 32 + g) * 8 + b) * 32 + lane) * 4 + (j & 1) * 2;
            __half2 w0 = __floats2half2_rn(sp0, sp1);
            __half2 w1 = __floats2half2_rn(sp2, sp3);
            *(uint2*)&g_hf[widx] = make_uint2(*(uint32_t*)&w0, *(uint32_t*)&w1);
        }
}

// ---------------- down-proj: persistent split-B, 512 threads (16 warps) ----------------
// grid (DD/64=16, NE=8) = 128 CTAs. B tile (64 x 512) split once into smem; loop m-tiles.
// Warp tile 32m x 16n -> 4 warps/SMSP, light registers, zero barriers in m-loop.
__global__ __launch_bounds__(512, 1)
void k_down(const float* __restrict__ dww, float* __restrict__ out) {
    const int e = blockIdx.y;
    const int dbase = blockIdx.x * 64;
    const int mt0 = g_off[e] >> 5, mt1 = g_off[e + 1] >> 5;
    if (mt0 >= mt1) return;

    extern __shared__ char smem[];
    const uint32_t sb = smem_u32(smem);
    const int tid = threadIdx.x, lane = tid & 31, warp = tid >> 5;
    const int wm = warp >> 2, wn = warp & 3;   // wm: 32-row group, wn: 16-col group

    // one-time: load + split whole B tile (64 rows x 512 k); 8 threads/row, 64 floats each
    {
        const int row = tid >> 3;
        const int seg = (tid & 7) * 64;
        const float* bp = dww + ((size_t)e * DD + dbase + row) * FF + seg;
        char* hb = smem + (uint32_t)row * DN_ROWB + seg * 2;
        char* lb = smem + DN_BL_OFF + (uint32_t)row * DN_ROWB + seg * 2;
        for (int k = 0; k < 64; k += 8) {
            float f[8];
            float4 v0 = *(const float4*)(bp + k);
            float4 v1 = *(const float4*)(bp + k + 4);
            f[0] = v0.x; f[1] = v0.y; f[2] = v0.z; f[3] = v0.w;
            f[4] = v1.x; f[5] = v1.y; f[6] = v1.z; f[7] = v1.w;
            uint32_t h[4], l[4];
            split8p(f, h, l);
            *(uint4*)(hb + k * 2) = make_uint4(h[0], h[1], h[2], h[3]);
            *(uint4*)(lb + k * 2) = make_uint4(l[0], l[1], l[2], l[3]);
        }
    }
    __syncthreads();

    const uint4* af = (const uint4*)g_hf;
    const int cg = lane & 3;
    const int srcb = (lane & 16) + cg;
    const int own_t = (lane >> 2) & 3;
    const uint32_t bcol = (uint32_t)(wn * 16 + (lane & 15)) * DN_ROWB;
    const uint32_t kphase = ((uint32_t)(lane >> 4) << 3) * 2;

    for (int tile_m = mt0; tile_m < mt1; tile_m++) {
        const int sbase = tile_m * 32;
        const size_t abase = (((size_t)tile_m * 32) * 8 + (wm * 2)) * 32 + lane;

        float acc[2][2][4];
#pragma unroll
        for (int im = 0; im < 2; im++)
#pragma unroll
            for (int j = 0; j < 2; j++)
#pragma unroll
                for (int q = 0; q < 4; q++) acc[im][j][q] = 0.f;

        uint4 Acur[4];
#pragma unroll
        for (int k16 = 0; k16 < 2; k16++)
#pragma unroll
            for (int im = 0; im < 2; im++)
                Acur[k16 * 2 + im] = af[abase + (size_t)k16 * 256 + im * 32];

        for (int p = 0; p < 16; p++) {
            uint4 Anext[4];
            if (p < 15) {
#pragma unroll
                for (int k16 = 0; k16 < 2; k16++)
#pragma unroll
                    for (int im = 0; im < 2; im++)
                        Anext[k16 * 2 + im] = af[abase + (size_t)(2 * (p + 1) + k16) * 256 + im * 32];
            }
#pragma unroll
            for (int k16 = 0; k16 < 2; k16++) {
                const uint32_t boff = bcol + (uint32_t)((2 * p + k16) * 16) * 2 + kphase;
                uint32_t as_[2][4], ass[2][4];
#pragma unroll
                for (int im = 0; im < 2; im++) {
                    const uint4 a = Acur[k16 * 2 + im];
                    as_[im][0] = a.x; as_[im][1] = a.y; as_[im][2] = a.z; as_[im][3] = a.w;
#pragma unroll
                    for (int q = 0; q < 4; q++) ass[im][q] = h2dn7(as_[im][q]);
                }
                uint32_t bh[2][2], bl[2][2];
                {
                    uint32_t r[4];
                    ldsm4(r, sb + boff);
                    bh[0][0] = r[0]; bh[0][1] = r[2];
                    bh[1][0] = r[1]; bh[1][1] = r[3];
                    ldsm4(r, sb + DN_BL_OFF + boff);
                    bl[0][0] = r[0]; bl[0][1] = r[2];
                    bl[1][0] = r[1]; bl[1][1] = r[3];
                }
#pragma unroll
                for (int im = 0; im < 2; im++)
#pragma unroll
                    for (int j = 0; j < 2; j++) {
                        mma16816(acc[im][j], as_[im], bh[j]);   // s*wh
                        mma16816(acc[im][j], ass[im], bl[j]);   // (s*2^-7)*(res_w*2^7)
                    }
            }
            if (p < 15) {
#pragma unroll
                for (int q = 0; q < 4; q++) Acur[q] = Anext[q];
            }
        }

        // epilogue: LIF + gated atomic scatter
#pragma unroll
        for (int im = 0; im < 2; im++)
#pragma unroll
            for (int j = 0; j < 2; j++) {
                float sp0, sp1, sp2, sp3;
                lif4(acc[im][j][0], acc[im][j][1], srcb, own_t, sp0, sp1);
                lif4(acc[im][j][2], acc[im][j][3], srcb, own_t, sp2, sp3);
                const int mloc = wm * 32 + im * 16 + (lane >> 2);
                const int col = dbase + wn * 16 + j * 8 + 2 * cg;
                {
                    const int slot = sbase + (mloc >> 2);
                    const int tok = g_tok[slot];
                    if (tok >= 0 && (sp0 != 0.f || sp1 != 0.f)) {
                        const float gate = g_gate[slot];
                        float* op = out + ((size_t)own_t * NN + tok) * DD + col;
                        if (sp0 != 0.f) atomicAdd(op, gate);
                        if (sp1 != 0.f) atomicAdd(op + 1, gate);
                    }
                }
                {
                    const int slot = sbase + ((mloc + 8) >> 2);
                    const int tok = g_tok[slot];
                    if (tok >= 0 && (sp2 != 0.f || sp3 != 0.f)) {
                        const float gate = g_gate[slot];
                        float* op = out + ((size_t)own_t * NN + tok) * DD + col;
                        if (sp2 != 0.f) atomicAdd(op, gate);
                        if (sp3 != 0.f) atomicAdd(op + 1, gate);
                    }
                }
            }
    }
}

// ---------------- launch ----------------
extern "C" void kernel_launch(void* const* d_in, const int* in_sizes, int n_in,
                              void* d_out, int out_size) {
    const float* x    = (const float*)d_in[0];
    const int*   idx  = (const int*)d_in[1];
    const float* wts  = (const float*)d_in[2];
    const float* upw  = (const float*)d_in[3];
    const float* dww  = (const float*)d_in[4];
    float* out = (float*)d_out;
    (void)in_sizes; (void)n_in; (void)out_size;

    cudaFuncSetAttribute(k_up,   cudaFuncAttributeMaxDynamicSharedMemorySize, UP_SMEM);
    cudaFuncSetAttribute(k_down, cudaFuncAttributeMaxDynamicSharedMemorySize, DN_SMEM);

    k_zero<<<4096, 256>>>((float4*)out, TT * NN * DD / 4);
    k_route<<<1, 512>>>(idx, wts);
    k_up<<<dim3(FF / 128, MTILES), 512, UP_SMEM>>>(x, upw);
    k_down<<<dim3(DD / 64, NE), 512, DN_SMEM>>>(dww, out);
}

// round 13
// speedup vs baseline: 1.3010x; 1.2423x over previous
#include <cuda_runtime.h>
#include <cuda_fp16.h>
#include <stdint.h>

// ---------------- problem constants ----------------
#define TT 4
#define NN 8192
#define DD 1024
#define NE 8
#define FF 512
#define KTOP 2
#define NSLOT   (NN * KTOP)              // 16384
#define MAXSLOT (NSLOT + NE * 32)        // 16640
#define MTILES  (MAXSLOT / 32)           // 520

#define BETA 0.9f
#define THRESH 1.0f
#define LSC 128.0f                        // 2^7 residual scale

// k_up smem: rows padded to 40 halves (80B) -> conflict-free ldmatrix
#define RPAD 40
#define T128 (128 * RPAD * 2)            // 10240
#define UP_SA_H 0
#define UP_SA_L (1 * T128)
#define UP_SB_H (2 * T128)
#define UP_SB_L (3 * T128)
#define UP_STRIDE (4 * T128)             // 40960
#define UP_SMEM (2 * UP_STRIDE)          // 81920
#define BTB (64 * RPAD * 2)              // 5120
#define DN_STAGE (2 * BTB)               // 10240: Bh, Bl
#define DN_SMEM (2 * DN_STAGE)           // 20480

// ---------------- scratch ----------------
__device__ __half g_uh[(size_t)NE * FF * DD];   // up_w split high
__device__ __half g_ul[(size_t)NE * FF * DD];   // up_w residual * 2^7
__device__ __half g_dh[(size_t)NE * DD * FF];   // down_w split high
__device__ __half g_dl[(size_t)NE * DD * FF];   // down_w residual * 2^7
// spikes in MMA A-fragment layout: [tile_m][gk(32)][b(8)][lane(32)][w(4)] u32 words
__device__ uint32_t g_hf[(size_t)MTILES * 32 * 8 * 32 * 4];
__device__ int   g_tok[MAXSLOT];
__device__ float g_gate[MAXSLOT];
__device__ int   g_exp[MAXSLOT];
__device__ int   g_cur[NE];
__device__ int   g_off[NE + 1];

// ---------------- helpers ----------------
__device__ __forceinline__ uint32_t smem_u32(const void* p) {
    uint32_t a;
    asm("{ .reg .u64 t; cvta.to.shared.u64 t, %1; cvt.u32.u64 %0, t; }" : "=r"(a) : "l"(p));
    return a;
}
__device__ __forceinline__ void ldsm4(uint32_t* r, uint32_t a) {
    asm volatile("ldmatrix.sync.aligned.m8n8.x4.shared.b16 {%0,%1,%2,%3}, [%4];"
        : "=r"(r[0]), "=r"(r[1]), "=r"(r[2]), "=r"(r[3]) : "r"(a));
}
__device__ __forceinline__ void mma16816(float* c, const uint32_t* a, const uint32_t* b) {
    asm volatile("mma.sync.aligned.m16n8k16.row.col.f32.f16.f16.f32 "
        "{%0,%1,%2,%3},{%4,%5,%6,%7},{%8,%9},{%0,%1,%2,%3};"
        : "+f"(c[0]), "+f"(c[1]), "+f"(c[2]), "+f"(c[3])
        : "r"(a[0]), "r"(a[1]), "r"(a[2]), "r"(a[3]), "r"(b[0]), "r"(b[1]));
}
// packed fp16 multiply by 2^-7 (exact exponent shift in normal range)
__device__ __forceinline__ uint32_t h2dn7(uint32_t a) {
    uint32_t r;
    asm("mul.f16x2 %0, %1, %2;" : "=r"(r) : "r"(a), "r"(0x20002000u));
    return r;
}

// split 8 fp32 -> h (4 u32 packed fp16x2) and l = rn16((v-h)*2^7) (4 u32)
__device__ __forceinline__ void split8p(const float* f, uint32_t* hp, uint32_t* lp) {
#pragma unroll
    for (int i = 0; i < 4; i++) {
        float f0 = f[2 * i], f1 = f[2 * i + 1];
        __half2 hh = __floats2half2_rn(f0, f1);
        float r0 = (f0 - __low2float(hh)) * LSC;
        float r1 = (f1 - __high2float(hh)) * LSC;
        __half2 ll = __floats2half2_rn(r0, r1);
        hp[i] = *(uint32_t*)&hh;
        lp[i] = *(uint32_t*)&ll;
    }
}

// LIF across 4 timestep-lanes (stride-4 shuffle); returns this lane's own-t spikes
__device__ __forceinline__ void lif4(float v0, float v1, int srcb, int own_t,
                                     float& sp0, float& sp1) {
    float m0 = 0.f, m1 = 0.f;
    sp0 = 0.f; sp1 = 0.f;
#pragma unroll
    for (int t4 = 0; t4 < 4; t4++) {
        float u0 = __shfl_sync(0xffffffffu, v0, srcb + 4 * t4);
        float u1 = __shfl_sync(0xffffffffu, v1, srcb + 4 * t4);
        m0 = BETA * m0 + u0; float s0 = (m0 > THRESH) ? 1.f : 0.f; m0 -= s0 * THRESH;
        m1 = BETA * m1 + u1; float s1 = (m1 > THRESH) ? 1.f : 0.f; m1 -= s1 * THRESH;
        if (t4 == own_t) { sp0 = s0; sp1 = s1; }
    }
}

// ---------------- one-time weight split prep ----------------
__device__ __forceinline__ void split_body(const float* src, __half* dh_, __half* dl_, int n4) {
    int stride = gridDim.x * blockDim.x;
    const float4* s4 = (const float4*)src;
    uint2* h2 = (uint2*)dh_;
    uint2* l2 = (uint2*)dl_;
    for (int i = blockIdx.x * blockDim.x + threadIdx.x; i < n4; i += stride) {
        float4 v = s4[i];
        __half2 hA = __floats2half2_rn(v.x, v.y);
        __half2 hB = __floats2half2_rn(v.z, v.w);
        __half2 lA = __floats2half2_rn((v.x - __low2float(hA)) * LSC, (v.y - __high2float(hA)) * LSC);
        __half2 lB = __floats2half2_rn((v.z - __low2float(hB)) * LSC, (v.w - __high2float(hB)) * LSC);
        h2[i] = make_uint2(*(uint32_t*)&hA, *(uint32_t*)&hB);
        l2[i] = make_uint2(*(uint32_t*)&lA, *(uint32_t*)&lB);
    }
}
__global__ void k_splitu(const float* w) { split_body(w, g_uh, g_ul, NE * FF * DD / 4); }
__global__ void k_splitd(const float* w) { split_body(w, g_dh, g_dl, NE * DD * FF / 4); }

// ---------------- routing / zero ----------------
__global__ void k_route(const int* __restrict__ idx, const float* __restrict__ wts) {
    __shared__ int scnt[NE];
    int tid = threadIdx.x;
    if (tid < NE) scnt[tid] = 0;
    __syncthreads();
    for (int i = tid; i < NSLOT; i += 512) atomicAdd(&scnt[idx[i]], 1);
    __syncthreads();
    if (tid == 0) {
        int off = 0;
        for (int e = 0; e < NE; e++) {
            g_off[e] = off; g_cur[e] = off;
            off += (scnt[e] + 31) & ~31;
        }
        g_off[NE] = off;
    }
    __syncthreads();
    for (int s = tid; s < MAXSLOT; s += 512) {
        g_tok[s] = -1; g_gate[s] = 0.f;
        int e = 0;
#pragma unroll
        for (int q = 1; q < NE; q++) if (s >= g_off[q]) e = q;
        g_exp[s] = e;
    }
    __syncthreads();
    for (int i = tid; i < NSLOT; i += 512) {
        int e = idx[i];
        int p = atomicAdd(&g_cur[e], 1);
        g_tok[p] = i >> 1;
        g_gate[p] = wts[i];
    }
}
__global__ void k_zero(float4* out, int n4) {
    int stride = gridDim.x * blockDim.x;
    for (int i = blockIdx.x * blockDim.x + threadIdx.x; i < n4; i += stride)
        out[i] = make_float4(0.f, 0.f, 0.f, 0.f);
}

// ---------------- up compute chunk (r10, unchanged) ----------------
__device__ __forceinline__ void comp_up(uint32_t bufb, int lane, int wm, int wn,
                                        float (&acc)[2][4][4]) {
#pragma unroll
    for (int k16 = 0; k16 < 2; k16++) {
        uint32_t koff = k16 * 16 + ((lane >> 4) << 3);
        uint32_t aoff = ((wm * 32 + (lane & 15)) * RPAD + koff) * 2;
        uint32_t ah[2][4], al[2][4];
        ldsm4(ah[0], bufb + UP_SA_H + aoff);
        ldsm4(ah[1], bufb + UP_SA_H + aoff + 16 * RPAD * 2);
        ldsm4(al[0], bufb + UP_SA_L + aoff);
        ldsm4(al[1], bufb + UP_SA_L + aoff + 16 * RPAD * 2);
        uint32_t boff = ((wn * 32 + (lane & 15)) * RPAD + koff) * 2;
        uint32_t bh[4][2], bl[4][2], bhs[4][2];
#pragma unroll
        for (int g = 0; g < 2; g++) {
            uint32_t r[4];
            ldsm4(r, bufb + UP_SB_H + boff + g * 16 * RPAD * 2);
            bh[2 * g][0] = r[0]; bh[2 * g][1] = r[2];
            bh[2 * g + 1][0] = r[1]; bh[2 * g + 1][1] = r[3];
            ldsm4(r, bufb + UP_SB_L + boff + g * 16 * RPAD * 2);
            bl[2 * g][0] = r[0]; bl[2 * g][1] = r[2];
            bl[2 * g + 1][0] = r[1]; bl[2 * g + 1][1] = r[3];
        }
        uint32_t ahs[2][4];
#pragma unroll
        for (int im = 0; im < 2; im++)
#pragma unroll
            for (int q = 0; q < 4; q++) ahs[im][q] = h2dn7(ah[im][q]);
#pragma unroll
        for (int j = 0; j < 4; j++) { bhs[j][0] = h2dn7(bh[j][0]); bhs[j][1] = h2dn7(bh[j][1]); }
#pragma unroll
        for (int im = 0; im < 2; im++)
#pragma unroll
            for (int j = 0; j < 4; j++) {
                mma16816(acc[im][j], ah[im], bh[j]);    // xh*wh
                mma16816(acc[im][j], ahs[im], bl[j]);   // (xh*2^-7)*(res_w*2^7)
                mma16816(acc[im][j], al[im], bhs[j]);   // (res_x*2^7)*(wh*2^-7)
            }
    }
}

// ---------------- up-proj + LIF -> fragment-layout fp16 spikes ----------------
// grid (FF/128=4, MTILES), 512 thr. A: fp32 x + in-loop split (r10 path).
// B: pre-split fp16 from g_uh/g_ul (pure uint4 copies).
__global__ __launch_bounds__(512, 1)
void k_up(const float* __restrict__ x) {
    const int tile_m = blockIdx.y, sbase = tile_m * 32;
    if (sbase >= g_off[NE]) return;
    const int e = g_exp[sbase];
    const int fbase = blockIdx.x * 128;

    extern __shared__ char smem[];
    const uint32_t sb = smem_u32(smem);
    const int tid = threadIdx.x, lane = tid & 31, warp = tid >> 5;
    const int wm = warp >> 2, wn = warp & 3;

    // A loader: 4 threads/row, 8 floats each (fp32 + split, r10)
    const int lrowA = tid >> 2, aq = (tid & 3) * 8;
    int tok = g_tok[sbase + (lrowA >> 2)];
    if (tok < 0) tok = 0;
    const float* aptr = x + ((size_t)(lrowA & 3) * NN + tok) * DD + aq;
    const uint32_t stsA = (uint32_t)(lrowA * RPAD + aq) * 2;
    // B loader: 4 threads/row, 8 halves (1 uint4) each from g_uh and g_ul
    const int lrowB = tid >> 2, bq = (tid & 3) * 8;
    const __half* bph = g_uh + ((size_t)e * FF + fbase + lrowB) * DD + bq;
    const __half* bpl = g_ul + ((size_t)e * FF + fbase + lrowB) * DD + bq;
    const uint32_t stsB = (uint32_t)(lrowB * RPAD + bq) * 2;

    float acc[2][4][4];
#pragma unroll
    for (int im = 0; im < 2; im++)
#pragma unroll
        for (int j = 0; j < 4; j++)
#pragma unroll
            for (int q = 0; q < 4; q++) acc[im][j][q] = 0.f;

    float fA[8];
    uint4 rBh, rBl;
#pragma unroll
    for (int q = 0; q < 2; q++) {
        float4 v = *(const float4*)(aptr + q * 4);
        fA[4 * q] = v.x; fA[4 * q + 1] = v.y; fA[4 * q + 2] = v.z; fA[4 * q + 3] = v.w;
    }
    rBh = *(const uint4*)bph;
    rBl = *(const uint4*)bpl;
    {
        uint32_t h[4], l[4];
        split8p(fA, h, l);
        *(uint4*)(smem + UP_SA_H + stsA) = make_uint4(h[0], h[1], h[2], h[3]);
        *(uint4*)(smem + UP_SA_L + stsA) = make_uint4(l[0], l[1], l[2], l[3]);
        *(uint4*)(smem + UP_SB_H + stsB) = rBh;
        *(uint4*)(smem + UP_SB_L + stsB) = rBl;
    }
    __syncthreads();

    const int NC = DD / 32;   // 32
    for (int c = 0; c < NC; c++) {
        const int buf = c & 1;
        if (c + 1 < NC) {
#pragma unroll
            for (int q = 0; q < 2; q++) {
                float4 v = *(const float4*)(aptr + (c + 1) * 32 + q * 4);
                fA[4 * q] = v.x; fA[4 * q + 1] = v.y; fA[4 * q + 2] = v.z; fA[4 * q + 3] = v.w;
            }
            rBh = *(const uint4*)(bph + (c + 1) * 32);
            rBl = *(const uint4*)(bpl + (c + 1) * 32);
        }
        comp_up(sb + buf * UP_STRIDE, lane, wm, wn, acc);
        if (c + 1 < NC) {
            char* nb = smem + (buf ^ 1) * UP_STRIDE;
            uint32_t h[4], l[4];
            split8p(fA, h, l);
            *(uint4*)(nb + UP_SA_H + stsA) = make_uint4(h[0], h[1], h[2], h[3]);
            *(uint4*)(nb + UP_SA_L + stsA) = make_uint4(l[0], l[1], l[2], l[3]);
            *(uint4*)(nb + UP_SB_H + stsB) = rBh;
            *(uint4*)(nb + UP_SB_L + stsB) = rBl;
        }
        __syncthreads();
    }

    const int cg = lane & 3;
    const int srcb = (lane & 16) + cg;
    const int own_t = (lane >> 2) & 3;
#pragma unroll
    for (int im = 0; im < 2; im++)
#pragma unroll
        for (int j = 0; j < 4; j++) {
            float sp0, sp1, sp2, sp3;
            lif4(acc[im][j][0], acc[im][j][1], srcb, own_t, sp0, sp1);
            lif4(acc[im][j][2], acc[im][j][3], srcb, own_t, sp2, sp3);
            const int g = blockIdx.x * 8 + wn * 2 + (j >> 1);
            const int b = wm * 2 + im;
            const size_t widx = ((((size_t)tile_m * 32 + g) * 8 + b) * 32 + lane) * 4 + (j & 1) * 2;
            __half2 w0 = __floats2half2_rn(sp0, sp1);
            __half2 w1 = __floats2half2_rn(sp2, sp3);
            *(uint2*)&g_hf[widx] = make_uint2(*(uint32_t*)&w0, *(uint32_t*)&w1);
        }
}

// ---------------- down-proj + LIF + gated scatter ----------------
// grid (DD/64=16, MTILES), 256 thr. A = spike frags via LDG; B pre-split fp16 copies.
// ass = as_ & 0x20002000 (exact: spike halves are 0x3C00/0x0000 -> 0x2000 = 2^-7).
__global__ __launch_bounds__(256, 2)
void k_down(float* __restrict__ out) {
    const int tile_m = blockIdx.y, sbase = tile_m * 32;
    if (sbase >= g_off[NE]) return;
    const int e = g_exp[sbase];
    const int dbase = blockIdx.x * 64;

    extern __shared__ char smem[];
    const uint32_t sb = smem_u32(smem);
    const int tid = threadIdx.x, lane = tid & 31, warp = tid >> 5;
    const int wm = warp >> 1, wn = warp & 1;

    // B loader: 4 threads/row, 8 halves each from g_dh and g_dl
    const int lrowB = tid >> 2, lqB = (tid & 3) * 8;
    const __half* bph = g_dh + ((size_t)e * DD + dbase + lrowB) * FF + lqB;
    const __half* bpl = g_dl + ((size_t)e * DD + dbase + lrowB) * FF + lqB;
    const uint32_t stsB = (uint32_t)(lrowB * RPAD + lqB) * 2;

    const uint4* af = (const uint4*)g_hf;
    const size_t abase = (((size_t)tile_m * 32) * 8 + (wm * 2)) * 32 + lane;

    float acc[2][4][4];
#pragma unroll
    for (int im = 0; im < 2; im++)
#pragma unroll
        for (int j = 0; j < 4; j++)
#pragma unroll
            for (int q = 0; q < 4; q++) acc[im][j][q] = 0.f;

    uint4 rBh = *(const uint4*)bph;
    uint4 rBl = *(const uint4*)bpl;
    *(uint4*)(smem + stsB) = rBh;
    *(uint4*)(smem + BTB + stsB) = rBl;
    uint4 Acur[4];
#pragma unroll
    for (int k16 = 0; k16 < 2; k16++)
#pragma unroll
        for (int im = 0; im < 2; im++)
            Acur[k16 * 2 + im] = af[abase + (size_t)k16 * 256 + im * 32];
    __syncthreads();

    const int NC = FF / 32;   // 16
    for (int c = 0; c < NC; c++) {
        const int buf = c & 1;
        uint4 Anext[4];
        if (c + 1 < NC) {
            rBh = *(const uint4*)(bph + (c + 1) * 32);
            rBl = *(const uint4*)(bpl + (c + 1) * 32);
#pragma unroll
            for (int k16 = 0; k16 < 2; k16++)
#pragma unroll
                for (int im = 0; im < 2; im++)
                    Anext[k16 * 2 + im] = af[abase + (size_t)(2 * (c + 1) + k16) * 256 + im * 32];
        }
        const uint32_t bufb = sb + buf * DN_STAGE;
#pragma unroll
        for (int k16 = 0; k16 < 2; k16++) {
            const uint32_t koff2 = (uint32_t)(k16 * 16 + ((lane >> 4) << 3)) * 2;
            const uint32_t boff = (uint32_t)(wn * 32 + (lane & 15)) * RPAD * 2 + koff2;
            uint32_t as_[2][4], ass[2][4];
#pragma unroll
            for (int im = 0; im < 2; im++) {
                const uint4 a = Acur[k16 * 2 + im];
                as_[im][0] = a.x; as_[im][1] = a.y; as_[im][2] = a.z; as_[im][3] = a.w;
#pragma unroll
                for (int q = 0; q < 4; q++) ass[im][q] = as_[im][q] & 0x20002000u;
            }
            uint32_t bh[4][2], bl[4][2];
#pragma unroll
            for (int g = 0; g < 2; g++) {
                uint32_t r[4];
                ldsm4(r, bufb + boff + g * 16 * RPAD * 2);
                bh[2 * g][0] = r[0]; bh[2 * g][1] = r[2];
                bh[2 * g + 1][0] = r[1]; bh[2 * g + 1][1] = r[3];
                ldsm4(r, bufb + BTB + boff + g * 16 * RPAD * 2);
                bl[2 * g][0] = r[0]; bl[2 * g][1] = r[2];
                bl[2 * g + 1][0] = r[1]; bl[2 * g + 1][1] = r[3];
            }
#pragma unroll
            for (int im = 0; im < 2; im++)
#pragma unroll
                for (int j = 0; j < 4; j++) {
                    mma16816(acc[im][j], as_[im], bh[j]);   // s*wh
                    mma16816(acc[im][j], ass[im], bl[j]);   // (s*2^-7)*(res_w*2^7)
                }
        }
        if (c + 1 < NC) {
            char* nb = smem + (buf ^ 1) * DN_STAGE;
            *(uint4*)(nb + stsB) = rBh;
            *(uint4*)(nb + BTB + stsB) = rBl;
#pragma unroll
            for (int q = 0; q < 4; q++) Acur[q] = Anext[q];
        }
        __syncthreads();
    }

    // epilogue: LIF + gated atomic scatter
    const int cg = lane & 3;
    const int srcb = (lane & 16) + cg;
    const int own_t = (lane >> 2) & 3;
#pragma unroll
    for (int im = 0; im < 2; im++)
#pragma unroll
        for (int j = 0; j < 4; j++) {
            float sp0, sp1, sp2, sp3;
            lif4(acc[im][j][0], acc[im][j][1], srcb, own_t, sp0, sp1);
            lif4(acc[im][j][2], acc[im][j][3], srcb, own_t, sp2, sp3);
            const int mloc = wm * 32 + im * 16 + (lane >> 2);
            const int col = dbase + wn * 32 + j * 8 + 2 * cg;
            {
                const int slot = sbase + (mloc >> 2);
                const int tok = g_tok[slot];
                if (tok >= 0 && (sp0 != 0.f || sp1 != 0.f)) {
                    const float gate = g_gate[slot];
                    float* op = out + ((size_t)own_t * NN + tok) * DD + col;
                    if (sp0 != 0.f) atomicAdd(op, gate);
                    if (sp1 != 0.f) atomicAdd(op + 1, gate);
                }
            }
            {
                const int slot = sbase + ((mloc + 8) >> 2);
                const int tok = g_tok[slot];
                if (tok >= 0 && (sp2 != 0.f || sp3 != 0.f)) {
                    const float gate = g_gate[slot];
                    float* op = out + ((size_t)own_t * NN + tok) * DD + col;
                    if (sp2 != 0.f) atomicAdd(op, gate);
                    if (sp3 != 0.f) atomicAdd(op + 1, gate);
                }
            }
        }
}

// ---------------- launch ----------------
extern "C" void kernel_launch(void* const* d_in, const int* in_sizes, int n_in,
                              void* d_out, int out_size) {
    const float* x    = (const float*)d_in[0];
    const int*   idx  = (const int*)d_in[1];
    const float* wts  = (const float*)d_in[2];
    const float* upw  = (const float*)d_in[3];
    const float* dww  = (const float*)d_in[4];
    float* out = (float*)d_out;
    (void)in_sizes; (void)n_in; (void)out_size;

    cudaFuncSetAttribute(k_up,   cudaFuncAttributeMaxDynamicSharedMemorySize, UP_SMEM);
    cudaFuncSetAttribute(k_down, cudaFuncAttributeMaxDynamicSharedMemorySize, DN_SMEM);

    k_zero<<<4096, 256>>>((float4*)out, TT * NN * DD / 4);
    k_route<<<1, 512>>>(idx, wts);
    k_splitu<<<1024, 256>>>(upw);
    k_splitd<<<1024, 256>>>(dww);
    k_up<<<dim3(FF / 128, MTILES), 512, UP_SMEM>>>(x);
    k_down<<<dim3(DD / 64, MTILES), 256, DN_SMEM>>>(out);
}